// round 1
// baseline (speedup 1.0000x reference)
#include <cuda_runtime.h>

// ATSS positive-layer: exact grid-binned k-NN (k=9) + GIoU threshold mask.
// N=65536 predictions, NT=2048 targets, domain [0,1024)^2.

#define N_PRED 65536
#define N_TGT  2048
#define K      9
#define GRID_DIM 64
#define CELLS   (GRID_DIM * GRID_DIM)
#define CELL_SIZE 16.0f
#define INV_CELL  0.0625f   // exact power-of-two scale: mul is exact, so cell = floor(x/16)

__device__ int    g_cell_count[CELLS];
__device__ int    g_cell_fill[CELLS];
__device__ int    g_cell_start[CELLS + 1];
__device__ float2 g_xy[N_PRED];
__device__ int    g_pid[N_PRED];

__device__ __forceinline__ int cell_of(float x, float y) {
    int gx = (int)(x * INV_CELL);
    int gy = (int)(y * INV_CELL);
    gx = min(max(gx, 0), GRID_DIM - 1);
    gy = min(max(gy, 0), GRID_DIM - 1);
    return gy * GRID_DIM + gx;
}

__global__ void k_init() {
    int i = blockIdx.x * blockDim.x + threadIdx.x;
    if (i < CELLS) { g_cell_count[i] = 0; g_cell_fill[i] = 0; }
}

__global__ void k_count(const float* __restrict__ p) {
    int i = blockIdx.x * blockDim.x + threadIdx.x;
    if (i >= N_PRED) return;
    float x = p[i * 6 + 2], y = p[i * 6 + 3];
    atomicAdd(&g_cell_count[cell_of(x, y)], 1);
}

// Single-block exclusive scan over 4096 cell counts (256 threads x 16 each).
__global__ void k_scan() {
    __shared__ int part[256];
    int tid = threadIdx.x;
    int base = tid * 16;
    int loc[16];
    int s = 0;
#pragma unroll
    for (int i = 0; i < 16; i++) { loc[i] = s; s += g_cell_count[base + i]; }
    part[tid] = s;
    __syncthreads();
    for (int off = 1; off < 256; off <<= 1) {
        int v = (tid >= off) ? part[tid - off] : 0;
        __syncthreads();
        part[tid] += v;
        __syncthreads();
    }
    int pre = (tid == 0) ? 0 : part[tid - 1];
#pragma unroll
    for (int i = 0; i < 16; i++) g_cell_start[base + i] = pre + loc[i];
    if (tid == 255) g_cell_start[CELLS] = pre + s;
}

__global__ void k_scatter(const float* __restrict__ p) {
    int i = blockIdx.x * blockDim.x + threadIdx.x;
    if (i >= N_PRED) return;
    float x = p[i * 6 + 2], y = p[i * 6 + 3];
    int c = cell_of(x, y);
    int pos = g_cell_start[c] + atomicAdd(&g_cell_fill[c], 1);
    g_xy[pos]  = make_float2(x, y);
    g_pid[pos] = i;
}

// One thread per target: exact expanding-ring top-9 + GIoU mean/var mask.
__global__ void k_search(const float* __restrict__ p,
                         const float* __restrict__ t,
                         float* __restrict__ out) {
    int tg = blockIdx.x * blockDim.x + threadIdx.x;
    if (tg >= N_TGT) return;

    float tx = t[tg * 6 + 2], ty = t[tg * 6 + 3];
    float tw = t[tg * 6 + 4], th = t[tg * 6 + 5];

    float d2[K];
    int   id[K];
#pragma unroll
    for (int j = 0; j < K; j++) { d2[j] = __int_as_float(0x7f800000); id[j] = 0x7fffffff; }

    int gx = min(max((int)(tx * INV_CELL), 0), GRID_DIM - 1);
    int gy = min(max((int)(ty * INV_CELL), 0), GRID_DIM - 1);

    auto process_cell = [&](int c) {
        int s = g_cell_start[c], e = g_cell_start[c + 1];
        for (int k = s; k < e; k++) {
            float2 xy = g_xy[k];
            // d^2 in the reference's exact op order: (t-p)^2 via mul,mul,add (no fma contraction)
            float dx = __fsub_rn(tx, xy.x);
            float dy = __fsub_rn(ty, xy.y);
            float d  = __fadd_rn(__fmul_rn(dx, dx), __fmul_rn(dy, dy));
            int   i  = g_pid[k];
            // lexicographic (d, index) beats current worst?
            if (d < d2[K - 1] || (d == d2[K - 1] && i < id[K - 1])) {
                float nd = d; int ni = i;
#pragma unroll
                for (int j = 0; j < K; j++) {
                    bool sw = (nd < d2[j]) || (nd == d2[j] && ni < id[j]);
                    float td = d2[j]; int ti = id[j];
                    if (sw) { d2[j] = nd; id[j] = ni; nd = td; ni = ti; }
                }
            }
        }
    };

    for (int r = 0; r <= GRID_DIM; r++) {
        int x0 = gx - r, x1 = gx + r;
        int y0 = gy - r, y1 = gy + r;
        int cy0 = max(y0, 0), cy1 = min(y1, GRID_DIM - 1);
        for (int yy = cy0; yy <= cy1; yy++) {
            if (yy == y0 || yy == y1) {
                int cx0 = max(x0, 0), cx1 = min(x1, GRID_DIM - 1);
                for (int xx = cx0; xx <= cx1; xx++) process_cell(yy * GRID_DIM + xx);
            } else {
                if (x0 >= 0)       process_cell(yy * GRID_DIM + x0);
                if (x1 < GRID_DIM) process_cell(yy * GRID_DIM + x1);
            }
        }
        // Any point in ring >= r+1 lies outside square [(gx-r)*16,(gx+r+1)*16) x (same y):
        // its distance is >= min distance from target to that square's boundary.
        float bx0 = tx - (float)(gx - r) * CELL_SIZE;
        float bx1 = (float)(gx + r + 1) * CELL_SIZE - tx;
        float by0 = ty - (float)(gy - r) * CELL_SIZE;
        float by1 = (float)(gy + r + 1) * CELL_SIZE - ty;
        float b = fminf(fminf(bx0, bx1), fminf(by0, by1));
        if (d2[K - 1] < b * b * 0.9999f) break;   // conservative margin
    }

    // ---- GIoU vs the 9 candidates (ascending-distance order, matching top_k) ----
    float b1x1 = tx - tw * 0.5f, b1x2 = tx + tw * 0.5f;
    float b1y1 = ty - th * 0.5f, b1y2 = ty + th * 0.5f;
    float w1 = b1x2 - b1x1, h1 = b1y2 - b1y1;

    float cbx[K], cby[K], cbw[K], cbh[K], gi[K];
#pragma unroll
    for (int j = 0; j < K; j++) {
        int base = id[j] * 6;
        cbx[j] = p[base + 2];
        cby[j] = p[base + 3];
        cbw[j] = p[base + 4];
        cbh[j] = p[base + 5];
    }

    float gsum = 0.0f;
#pragma unroll
    for (int j = 0; j < K; j++) {
        float b2x1 = cbx[j] - cbw[j] * 0.5f, b2x2 = cbx[j] + cbw[j] * 0.5f;
        float b2y1 = cby[j] - cbh[j] * 0.5f, b2y2 = cby[j] + cbh[j] * 0.5f;
        float iw = fmaxf(fminf(b1x2, b2x2) - fmaxf(b1x1, b2x1), 0.0f);
        float ih = fmaxf(fminf(b1y2, b2y2) - fmaxf(b1y1, b2y1), 0.0f);
        float inter = iw * ih;
        float w2 = b2x2 - b2x1, h2 = b2y2 - b2y1;
        float uni = ((w1 * h1 + 1e-16f) + w2 * h2) - inter;
        float iou = inter / uni;
        float cw = fmaxf(b1x2, b2x2) - fminf(b1x1, b2x1);
        float ch = fmaxf(b1y2, b2y2) - fminf(b1y1, b2y1);
        float ca = cw * ch + 1e-16f;
        gi[j] = iou - (ca - uni) / ca;
        gsum += gi[j];
    }
    float mean = gsum / 9.0f;
    float s2 = 0.0f;
#pragma unroll
    for (int j = 0; j < K; j++) { float d = gi[j] - mean; s2 += d * d; }
    float thr = mean + s2 / 8.0f;   // ddof=1

    float4* out4 = (float4*)(out + tg * (K * 4));
#pragma unroll
    for (int j = 0; j < K; j++) {
        float m = (gi[j] > thr) ? 1.0f : 0.0f;
        out4[j] = make_float4(cbx[j] * m, cby[j] * m, cbw[j] * m, cbh[j] * m);
    }
}

extern "C" void kernel_launch(void* const* d_in, const int* in_sizes, int n_in,
                              void* d_out, int out_size) {
    (void)in_sizes; (void)n_in; (void)out_size;
    const float* p = (const float*)d_in[0];
    const float* t = (const float*)d_in[1];
    float* out = (float*)d_out;

    k_init<<<CELLS / 256, 256>>>();
    k_count<<<N_PRED / 256, 256>>>(p);
    k_scan<<<1, 256>>>();
    k_scatter<<<N_PRED / 256, 256>>>(p);
    k_search<<<N_TGT / 32, 32>>>(p, t, out);
}

// round 2
// speedup vs baseline: 6.3758x; 6.3758x over previous
#include <cuda_runtime.h>

// ATSS positive-layer: single-pass grid binning (fixed-capacity cells + exact
// overflow list) + warp-cooperative exact k-NN (k=9) + GIoU threshold mask.
// N=65536 predictions, NT=2048 targets, domain [0,1024)^2.

#define N_PRED 65536
#define N_TGT  2048
#define K      9
#define GRID_DIM 64
#define CELLS   (GRID_DIM * GRID_DIM)
#define CAP     64
#define CELL_SIZE 16.0f
#define INV_CELL  0.0625f   // exact power-of-two scale

__device__ int    g_fill[CELLS];
__device__ int    g_ovf_cnt;
__device__ float2 g_xy[CELLS * CAP];
__device__ int    g_pid[CELLS * CAP];
__device__ float2 g_oxy[N_PRED];   // overflow (exact fallback; empty in practice)
__device__ int    g_opid[N_PRED];

__device__ __forceinline__ int cell_of(float x, float y) {
    int gx = (int)(x * INV_CELL);
    int gy = (int)(y * INV_CELL);
    gx = min(max(gx, 0), GRID_DIM - 1);
    gy = min(max(gy, 0), GRID_DIM - 1);
    return gy * GRID_DIM + gx;
}

// 64-bit lexicographic key: (d2 float bits, idx). d2 >= 0 so float bits are
// order-preserving. Smaller key == (smaller d2) or (equal d2, smaller idx),
// matching jax top_k's stable ordering on -dist.
__device__ __forceinline__ unsigned long long pack_key(float d2, int idx) {
    return ((unsigned long long)__float_as_uint(d2) << 32) | (unsigned)idx;
}

__global__ void k_init() {
    int i = blockIdx.x * blockDim.x + threadIdx.x;
    if (i < CELLS) g_fill[i] = 0;
    if (i == 0) g_ovf_cnt = 0;
}

// One thread scatters 2 boxes (two float4 loads, middle quad unused).
__global__ void k_scatter(const float* __restrict__ p) {
    int i = blockIdx.x * blockDim.x + threadIdx.x;   // i < N_PRED/2
    const float4* p4 = (const float4*)p;
    float4 a = p4[i * 3];       // box 2i   fields 0..3 -> x=.z y=.w
    float4 b = p4[i * 3 + 2];   // box 2i+1 fields 2..5 -> x=.x y=.y
    float xs[2] = {a.z, b.x};
    float ys[2] = {a.w, b.y};
#pragma unroll
    for (int j = 0; j < 2; j++) {
        int id = 2 * i + j;
        int c = cell_of(xs[j], ys[j]);
        int slot = atomicAdd(&g_fill[c], 1);
        if (slot < CAP) {
            g_xy[c * CAP + slot]  = make_float2(xs[j], ys[j]);
            g_pid[c * CAP + slot] = id;
        } else {
            int o = atomicAdd(&g_ovf_cnt, 1);
            g_oxy[o]  = make_float2(xs[j], ys[j]);
            g_opid[o] = id;
        }
    }
}

// One WARP per target: lanes stride coalesced over cell points into lane-local
// top-9 (packed keys), 9-round warp-min merge, then GIoU mean/var mask.
__global__ void k_search(const float* __restrict__ p,
                         const float* __restrict__ t,
                         float* __restrict__ out) {
    const unsigned FULL = 0xffffffffu;
    int gwid = (blockIdx.x * blockDim.x + threadIdx.x) >> 5;
    int lane = threadIdx.x & 31;
    if (gwid >= N_TGT) return;
    int tg = gwid;

    float tx = t[tg * 6 + 2], ty = t[tg * 6 + 3];
    float tw = t[tg * 6 + 4], th = t[tg * 6 + 5];

    const unsigned long long KMAX = 0xffffffffffffffffULL;
    unsigned long long lk[K];
#pragma unroll
    for (int j = 0; j < K; j++) lk[j] = KMAX;

    int gx = min(max((int)(tx * INV_CELL), 0), GRID_DIM - 1);
    int gy = min(max((int)(ty * INV_CELL), 0), GRID_DIM - 1);
    int x0 = max(gx - 1, 0), x1 = min(gx + 1, GRID_DIM - 1);
    int y0 = max(gy - 1, 0), y1 = min(gy + 1, GRID_DIM - 1);

    // d^2 in the reference's exact op order (mul, mul, add; no fma contraction)
    auto dist2 = [&](float px, float py) {
        float dx = __fsub_rn(tx, px);
        float dy = __fsub_rn(ty, py);
        return __fadd_rn(__fmul_rn(dx, dx), __fmul_rn(dy, dy));
    };
    auto local_insert = [&](unsigned long long key) {
        if (key < lk[K - 1]) {
            unsigned long long nk = key;
#pragma unroll
            for (int j = 0; j < K; j++) {
                if (nk < lk[j]) { unsigned long long tmp = lk[j]; lk[j] = nk; nk = tmp; }
            }
        }
    };

    // ---- lane-cooperative scan of 3x3 neighborhood ----
    for (int yy = y0; yy <= y1; yy++) {
        for (int xx = x0; xx <= x1; xx++) {
            int c = yy * GRID_DIM + xx;
            int cnt = min(g_fill[c], CAP);
            int base = c * CAP;
            for (int k = lane; k < cnt; k += 32) {
                float2 xy = g_xy[base + k];
                local_insert(pack_key(dist2(xy.x, xy.y), g_pid[base + k]));
            }
        }
    }
    // overflow list (normally empty; always scanning it is exact & conservative)
    int oc = g_ovf_cnt;
    for (int k = lane; k < oc; k += 32) {
        float2 xy = g_oxy[k];
        local_insert(pack_key(dist2(xy.x, xy.y), g_opid[k]));
    }

    // ---- 9-round warp-min merge -> replicated rkey[9] ----
    unsigned long long rkey[K];
#pragma unroll
    for (int j = 0; j < K; j++) {
        unsigned long long mykey = lk[0];
        unsigned long long kmin = mykey;
#pragma unroll
        for (int off = 16; off > 0; off >>= 1) {
            unsigned long long o = __shfl_xor_sync(FULL, kmin, off);
            if (o < kmin) kmin = o;
        }
        rkey[j] = kmin;
        if (mykey == kmin) {   // winner lane pops its head (static shift)
#pragma unroll
            for (int s = 0; s < K - 1; s++) lk[s] = lk[s + 1];
            lk[K - 1] = KMAX;
        }
    }

    // ---- exact ring expansion fallback (replicated, all lanes identical) ----
    auto scan_cell_repl = [&](int c) {
        int cnt = min(g_fill[c], CAP);
        int base = c * CAP;
        for (int k = 0; k < cnt; k++) {
            float2 xy = g_xy[base + k];
            unsigned long long key = pack_key(dist2(xy.x, xy.y), g_pid[base + k]);
            if (key < rkey[K - 1]) {
                unsigned long long nk = key;
#pragma unroll
                for (int j = 0; j < K; j++) {
                    if (nk < rkey[j]) { unsigned long long tmp = rkey[j]; rkey[j] = nk; nk = tmp; }
                }
            }
        }
    };
    while (true) {
        bool full = (x0 == 0) & (x1 == GRID_DIM - 1) & (y0 == 0) & (y1 == GRID_DIM - 1);
        float b = __int_as_float(0x7f800000);
        if (x0 > 0)            b = fminf(b, tx - (float)x0 * CELL_SIZE);
        if (x1 < GRID_DIM - 1) b = fminf(b, (float)(x1 + 1) * CELL_SIZE - tx);
        if (y0 > 0)            b = fminf(b, ty - (float)y0 * CELL_SIZE);
        if (y1 < GRID_DIM - 1) b = fminf(b, (float)(y1 + 1) * CELL_SIZE - ty);
        float d8 = __uint_as_float((unsigned)(rkey[K - 1] >> 32));
        if (full || d8 < b * b * 0.9999f) break;
        int nx0 = max(x0 - 1, 0), nx1 = min(x1 + 1, GRID_DIM - 1);
        int ny0 = max(y0 - 1, 0), ny1 = min(y1 + 1, GRID_DIM - 1);
        if (ny0 < y0) for (int xx = nx0; xx <= nx1; xx++) scan_cell_repl(ny0 * GRID_DIM + xx);
        if (ny1 > y1) for (int xx = nx0; xx <= nx1; xx++) scan_cell_repl(ny1 * GRID_DIM + xx);
        if (nx0 < x0) for (int yy = y0; yy <= y1; yy++)   scan_cell_repl(yy * GRID_DIM + nx0);
        if (nx1 > x1) for (int yy = y0; yy <= y1; yy++)   scan_cell_repl(yy * GRID_DIM + nx1);
        x0 = nx0; x1 = nx1; y0 = ny0; y1 = ny1;
    }

    // distribute candidate j to lane j (static, predicated)
    unsigned long long selkey = KMAX;
#pragma unroll
    for (int j = 0; j < K; j++) if (lane == j) selkey = rkey[j];

    // ---- GIoU for lane's candidate (lanes 0..8) ----
    float b1x1 = tx - tw * 0.5f, b1x2 = tx + tw * 0.5f;
    float b1y1 = ty - th * 0.5f, b1y2 = ty + th * 0.5f;
    float w1 = b1x2 - b1x1, h1 = b1y2 - b1y1;

    float gi = 0.0f, cbx = 0.0f, cby = 0.0f, cbw = 0.0f, cbh = 0.0f;
    if (lane < K) {
        int id = (int)(selkey & 0xffffffffu);
        int base = id * 6;
        cbx = p[base + 2]; cby = p[base + 3];
        cbw = p[base + 4]; cbh = p[base + 5];
        float b2x1 = cbx - cbw * 0.5f, b2x2 = cbx + cbw * 0.5f;
        float b2y1 = cby - cbh * 0.5f, b2y2 = cby + cbh * 0.5f;
        float iw = fmaxf(fminf(b1x2, b2x2) - fmaxf(b1x1, b2x1), 0.0f);
        float ih = fmaxf(fminf(b1y2, b2y2) - fmaxf(b1y1, b2y1), 0.0f);
        float inter = iw * ih;
        float w2 = b2x2 - b2x1, h2 = b2y2 - b2y1;
        float uni = ((w1 * h1 + 1e-16f) + w2 * h2) - inter;
        float iou = inter / uni;
        float cw = fmaxf(b1x2, b2x2) - fminf(b1x1, b2x1);
        float ch = fmaxf(b1y2, b2y2) - fminf(b1y1, b2y1);
        float ca = cw * ch + 1e-16f;
        gi = iou - (ca - uni) / ca;
    }

    // gather 9 giou values into every lane; sequential sums (same order as R1)
    float gg[K];
#pragma unroll
    for (int j = 0; j < K; j++) gg[j] = __shfl_sync(FULL, gi, j);
    float gsum = 0.0f;
#pragma unroll
    for (int j = 0; j < K; j++) gsum += gg[j];
    float mean = gsum / 9.0f;
    float s2 = 0.0f;
#pragma unroll
    for (int j = 0; j < K; j++) { float d = gg[j] - mean; s2 += d * d; }
    float thr = mean + s2 / 8.0f;   // ddof=1

    if (lane < K) {
        float m = (gi > thr) ? 1.0f : 0.0f;
        float4* out4 = (float4*)(out + tg * (K * 4));
        out4[lane] = make_float4(cbx * m, cby * m, cbw * m, cbh * m);
    }
}

extern "C" void kernel_launch(void* const* d_in, const int* in_sizes, int n_in,
                              void* d_out, int out_size) {
    (void)in_sizes; (void)n_in; (void)out_size;
    const float* p = (const float*)d_in[0];
    const float* t = (const float*)d_in[1];
    float* out = (float*)d_out;

    k_init<<<CELLS / 256, 256>>>();
    k_scatter<<<(N_PRED / 2) / 256, 256>>>(p);
    k_search<<<(N_TGT * 32) / 256, 256>>>(p, t, out);
}